// round 11
// baseline (speedup 1.0000x reference)
#include <cuda_runtime.h>
#include <cstdint>
#include <cstddef>

// IDGNN restructured (math validated R2-R10, rel_err ~2e-7):
//   p_i = MLP_{0,i}(x);  u = x + A*p0;  d = p1 - p0
//   Un_i = u*W1e[1,i]; Dt_i = d*W1e[1,i]  (K=256 view: X[k&127], no explicit fold)
//   S_t = sum_{n in N(t)} relu(Un0[n] + Dt0[t] + b1[1,0])
//   out[t] = u_t + self_t*d_t + S_t*w2[1,0] + deg_t*b2[1,0] + self-correction
// R11: weights staged into smem via cp.async.bulk + mbarrier double-buffer
// (6 x 64KB stages, one ahead), GEMMs read LDS.128 read-once. 128x512, 1 blk/SM.

#define NN 256
#define DD 128
#define NB 128
#define NT 512

__device__ unsigned g_adj[NN * 8];
__device__ __align__(16) float g_p0[NN * DD];
__device__ __align__(16) float g_p1[NN * DD];
__device__ __align__(16) float g_u [NN * DD];
__device__ __align__(16) float g_d [NN * DD];
__device__ __align__(16) float g_UD[4][NN * DD];   // 0:Un0 1:Dt0 2:Un1 3:Dt1
__device__ unsigned g_leaf[16 * 64];
__device__ unsigned g_root;
__device__ unsigned g_gen;

struct DynSmem {
    float WA[16384];            // 64KB weight buffer A
    float WB[16384];            // 64KB weight buffer B
    float part[16][4][DD];      // 32KB partials
    float X[4][DD];             // X / H / U / Ssum
    float D[4][DD];             // d / Hs
    int   nbr[4][NN];
    int   cnts[4];
    int   selfS[4];
    unsigned long long mbarA, mbarB;
    unsigned gen0;
};

__device__ __forceinline__ float4 f4add(float4 a, float4 b) {
    return make_float4(a.x + b.x, a.y + b.y, a.z + b.z, a.w + b.w);
}
__device__ __forceinline__ float4 f4fma(float s, float4 w, float4 a) {
    return make_float4(fmaf(s, w.x, a.x), fmaf(s, w.y, a.y),
                       fmaf(s, w.z, a.z), fmaf(s, w.w, a.w));
}
__device__ __forceinline__ float4 f4relu(float4 a) {
    return make_float4(fmaxf(a.x, 0.f), fmaxf(a.y, 0.f),
                       fmaxf(a.z, 0.f), fmaxf(a.w, 0.f));
}
__device__ __forceinline__ unsigned ldcg_u32(const unsigned* p) {
    unsigned v;
    asm volatile("ld.global.cg.u32 %0, [%1];" : "=r"(v) : "l"(p));
    return v;
}
__device__ __forceinline__ uint32_t s2u(const void* p) {
    uint32_t a;
    asm("{ .reg .u64 t; cvta.to.shared.u64 t, %1; cvt.u32.u64 %0, t; }"
        : "=r"(a) : "l"(p));
    return a;
}
__device__ __forceinline__ void mbar_init(uint32_t m, uint32_t cnt) {
    asm volatile("mbarrier.init.shared.b64 [%0], %1;" :: "r"(m), "r"(cnt) : "memory");
}
__device__ __forceinline__ void fence_async() {
    asm volatile("fence.proxy.async.shared::cta;" ::: "memory");
}
// expect_tx + bulk copy (64KB), single thread
__device__ __forceinline__ void stage64k(uint32_t mbar, uint32_t dst, const float* src) {
    asm volatile("mbarrier.arrive.expect_tx.shared.b64 _, [%0], %1;"
                 :: "r"(mbar), "r"(65536u) : "memory");
    asm volatile("cp.async.bulk.shared::cluster.global.mbarrier::complete_tx::bytes "
                 "[%0], [%1], %2, [%3];"
                 :: "r"(dst), "l"(src), "r"(65536u), "r"(mbar) : "memory");
}
__device__ __forceinline__ void mbar_wait(uint32_t m, uint32_t parity) {
    uint32_t done;
    asm volatile("{ .reg .pred p; mbarrier.try_wait.parity.acquire.cta.shared::cta.b64 "
                 "p, [%1], %2; selp.b32 %0,1,0,p; }"
                 : "=r"(done) : "r"(m), "r"(parity) : "memory");
    while (!done) {
        asm volatile("{ .reg .pred p; mbarrier.try_wait.parity.acquire.cta.shared::cta.b64 "
                     "p, [%1], %2, 0x989680; selp.b32 %0,1,0,p; }"
                     : "=r"(done) : "r"(m), "r"(parity) : "memory");
    }
}

// Hierarchical grid barrier: 16 leaves x 8 arrivals + 16-arrival root.
__device__ __forceinline__ void grid_sync(unsigned target, int bid) {
    __syncthreads();
    if (threadIdx.x == 0) {
        __threadfence();
        unsigned* leaf = &g_leaf[(bid & 15) * 64];
        unsigned a = atomicAdd(leaf, 1u);
        if (a == 7u) {
            atomicExch(leaf, 0u);
            unsigned rr = atomicAdd(&g_root, 1u);
            if (rr == 15u) {
                atomicExch(&g_root, 0u);
                __threadfence();
                atomicExch(&g_gen, target);
            }
        }
        while (ldcg_u32(&g_gen) != target) __nanosleep(32);
        __threadfence();
    }
    __syncthreads();
}

// Expand g_adj[row] bitmask into nbr[] (full warp). Returns count.
__device__ __forceinline__ int build_list(int row, int* nbr) {
    int lane = threadIdx.x & 31;
    unsigned word = (lane < 8) ? g_adj[row * 8 + lane] : 0u;
    int pc = __popc(word);
    int inc = pc;
#pragma unroll
    for (int off = 1; off < 8; off <<= 1) {
        int v = __shfl_up_sync(0xffffffffu, inc, off);
        if (lane >= off) inc += v;
    }
    int base = inc - pc;
    if (lane < 8) {
        unsigned bits = word; int o = base;
        while (bits) { int b = __ffs(bits) - 1; bits &= bits - 1; nbr[o++] = lane * 32 + b; }
    }
    return __shfl_sync(0xffffffffu, inc, 7);
}

extern __shared__ DynSmem smem[];

__global__ void __launch_bounds__(NT, 1)
k_fused(const int* __restrict__ ei32, int E,
        const float* __restrict__ xf, const float* __restrict__ w1,
        const float* __restrict__ b1, const float* __restrict__ w2,
        const float* __restrict__ b2, float* __restrict__ out) {
    DynSmem* sm = smem;
    const int tid = threadIdx.x, lane = tid & 31, w = tid >> 5, bid = blockIdx.x;
    const int i    = bid >> 6;                 // MLP instance 0/1
    const int row0 = (bid & 63) * 4;           // 4 rows per block
    const uint32_t aWA = s2u(sm->WA), aWB = s2u(sm->WB);
    const uint32_t mA = s2u(&sm->mbarA), mB = s2u(&sm->mbarB);
    const float4* WA4 = (const float4*)sm->WA;
    const float4* WB4 = (const float4*)sm->WB;

    // ---- init mbarriers, snapshot gen, kick off first two weight stages ----
    if (tid == 0) {
        mbar_init(mA, 1);
        mbar_init(mB, 1);
        sm->gen0 = ldcg_u32(&g_gen);
    }
    __syncthreads();
    if (tid == 0) {
        fence_async();
        stage64k(mA, aWA, w1 + i * 32768);            // w1[0,i] k 0..127
        stage64k(mB, aWB, w1 + i * 32768 + 16384);    // w1[0,i] k 128..255
    }
    const unsigned gen0 = sm->gen0;

    // ---- edge scatter (blocks 0-7) + load X ----
    if (bid < 8) {
        // dtype sniff: int64 node ids (<256, nonneg) => odd int32 words zero
        int probe = (2 * tid + 1 < 2 * E) ? ei32[2 * tid + 1] : 0;
        int is64 = __syncthreads_and(probe == 0);
        for (int e = bid * NT + tid; e < E; e += 8 * NT) {
            int a, b;
            if (is64) { a = ei32[2 * e]; b = ei32[2 * (E + e)]; }
            else      { a = ei32[e];     b = ei32[E + e]; }
            a &= 255; b &= 255;
            atomicOr(&g_adj[a * 8 + (b >> 5)], 1u << (b & 31));
            atomicOr(&g_adj[b * 8 + (a >> 5)], 1u << (a & 31));
        }
    }
    {   int r = tid >> 7, c = tid & 127;
        sm->X[r][c] = xf[(row0 + r) * DD + c];
    }
    __syncthreads();

    // ===== P1a: layer-0 L1 GEMM, K=256 in two chunks (X[k&127]) ============
    float4 acc[4] = {};
    mbar_wait(mA, 0);
#pragma unroll
    for (int kk = 0; kk < 8; kk++) {
        int k = w * 8 + kk;
        float4 wv = WA4[k * 32 + lane];
#pragma unroll
        for (int r = 0; r < 4; r++) acc[r] = f4fma(sm->X[r][k], wv, acc[r]);
    }
    __syncthreads();                                   // WA free
    if (tid == 0) stage64k(mA, aWA, w2 + i * 16384);   // w2[0,i]
    mbar_wait(mB, 0);
#pragma unroll
    for (int kk = 0; kk < 8; kk++) {
        int k = w * 8 + kk;
        float4 wv = WB4[k * 32 + lane];
#pragma unroll
        for (int r = 0; r < 4; r++) acc[r] = f4fma(sm->X[r][k], wv, acc[r]);
    }
#pragma unroll
    for (int r = 0; r < 4; r++) ((float4*)sm->part[w][r])[lane] = acc[r];
    __syncthreads();                                   // WB free, partials ready
    if (tid == 0) stage64k(mB, aWB, w1 + (2 + i) * 32768);   // w1[1,i] lo
    {   // H = relu(sum partials + b1[0,i]); overwrite X region
        int r = tid >> 7, c = tid & 127;
        float s = b1[i * DD + c];
#pragma unroll
        for (int ww = 0; ww < 16; ww++) s += sm->part[ww][r][c];
        sm->X[r][c] = fmaxf(s, 0.f);
    }
    __syncthreads();

    // ===== P1b: layer-0 L2 GEMM (w2[0,i] in WA) =============================
    mbar_wait(mA, 1);
    float4 acc2[4] = {};
#pragma unroll
    for (int kk = 0; kk < 8; kk++) {
        int k = w * 8 + kk;
        float4 wv = WA4[k * 32 + lane];
#pragma unroll
        for (int r = 0; r < 4; r++) acc2[r] = f4fma(sm->X[r][k], wv, acc2[r]);
    }
    __syncthreads();                                   // WA free
    if (tid == 0) stage64k(mA, aWA, w1 + (2 + i) * 32768 + 16384);  // w1[1,i] hi
#pragma unroll
    for (int r = 0; r < 4; r++) ((float4*)sm->part[w][r])[lane] = acc2[r];
    __syncthreads();
    {   int r = tid >> 7, c = tid & 127;
        float s = b2[i * DD + c];
#pragma unroll
        for (int ww = 0; ww < 16; ww++) s += sm->part[ww][r][c];
        (i ? g_p1 : g_p0)[(row0 + r) * DD + c] = s;
    }
    grid_sync(gen0 + 1, bid);

    // ===== P2: lists + d + u-gather + {U,D} x w1[1,i] (K=256, 2 chunks) ====
    if (w < 4) {
        int row = row0 + w;
        int cn = build_list(row, sm->nbr[w]);
        if (lane == 0) {
            sm->cnts[w]  = cn;
            sm->selfS[w] = (g_adj[row * 8 + (row >> 5)] >> (row & 31)) & 1;
        }
    } else {
        for (int v = tid - 128; v < 512; v += 384) {
            int r = v >> 7, c = v & 127;
            float dv = g_p1[(row0 + r) * DD + c] - g_p0[(row0 + r) * DD + c];
            sm->D[r][c] = dv;
            if (i == 0) g_d[(row0 + r) * DD + c] = dv;
        }
    }
    __syncthreads();
    {   // u-gather: warp (r = w&3, q = w>>2) splits list mod 4
        int r = w & 3, q = w >> 2;
        const float4* p04 = (const float4*)g_p0;
        int cn = sm->cnts[r];
        float4 s0 = {}, s1 = {};
        int j = q;
        for (; j + 4 < cn; j += 8) {
            s0 = f4add(s0, p04[sm->nbr[r][j]     * 32 + lane]);
            s1 = f4add(s1, p04[sm->nbr[r][j + 4] * 32 + lane]);
        }
        if (j < cn) s0 = f4add(s0, p04[sm->nbr[r][j] * 32 + lane]);
        ((float4*)sm->part[w][0])[lane] = f4add(s0, s1);
    }
    __syncthreads();
    {   int r = tid >> 7, c = tid & 127;
        float uv = xf[(row0 + r) * DD + c]
                 + sm->part[r][0][c] + sm->part[r + 4][0][c]
                 + sm->part[r + 8][0][c] + sm->part[r + 12][0][c];
        sm->X[r][c] = uv;                              // X region now U
        if (i == 0) g_u[(row0 + r) * DD + c] = uv;
    }
    __syncthreads();
    float4 aU[4] = {}, aD[4] = {};
    mbar_wait(mB, 1);                                  // w1[1,i] lo
#pragma unroll
    for (int kk = 0; kk < 8; kk++) {
        int k = w * 8 + kk;
        float4 wv = WB4[k * 32 + lane];
#pragma unroll
        for (int r = 0; r < 4; r++) {
            aU[r] = f4fma(sm->X[r][k], wv, aU[r]);
            aD[r] = f4fma(sm->D[r][k], wv, aD[r]);
        }
    }
    __syncthreads();                                   // WB free
    if (tid == 0) stage64k(mB, aWB, w2 + 2 * 16384);   // w2[1,0]
    mbar_wait(mA, 0);                                  // w1[1,i] hi (3rd use)
#pragma unroll
    for (int kk = 0; kk < 8; kk++) {
        int k = w * 8 + kk;
        float4 wv = WA4[k * 32 + lane];
#pragma unroll
        for (int r = 0; r < 4; r++) {
            aU[r] = f4fma(sm->X[r][k], wv, aU[r]);
            aD[r] = f4fma(sm->D[r][k], wv, aD[r]);
        }
    }
#pragma unroll
    for (int r = 0; r < 4; r++) ((float4*)sm->part[w][r])[lane] = aU[r];
    __syncthreads();
    {   int r = tid >> 7, c = tid & 127;
        float s = 0.f;
#pragma unroll
        for (int ww = 0; ww < 16; ww++) s += sm->part[ww][r][c];
        g_UD[2 * i][(row0 + r) * DD + c] = s;
    }
    __syncthreads();
#pragma unroll
    for (int r = 0; r < 4; r++) ((float4*)sm->part[w][r])[lane] = aD[r];
    __syncthreads();
    {   int r = tid >> 7, c = tid & 127;
        float s = 0.f;
#pragma unroll
        for (int ww = 0; ww < 16; ww++) s += sm->part[ww][r][c];
        g_UD[2 * i + 1][(row0 + r) * DD + c] = s;
    }
    grid_sync(gen0 + 2, bid);

    // ===== P3: 2 rows/block (rows row0+2i, row0+2i+1) =======================
    {   // relu-gather: warp (rr = w&1, q = w>>1) splits list mod 8
        int rr = w & 1, q = w >> 1;
        int lst = 2 * i + rr, row = row0 + lst;
        const float4* UD0 = (const float4*)g_UD[0];
        float4 pre = f4add(((const float4*)g_UD[1])[row * 32 + lane],
                           ((const float4*)(b1 + 2 * DD))[lane]);
        int cn = sm->cnts[lst];
        float4 s0 = {};
        for (int j = q; j < cn; j += 8)
            s0 = f4add(s0, f4relu(f4add(UD0[sm->nbr[lst][j] * 32 + lane], pre)));
        ((float4*)sm->part[w][0])[lane] = s0;
    }
    __syncthreads();
    if (tid < 256) {                                   // Ssum reduce (no sync inside)
        int rr = tid >> 7, c = tid & 127;
        float s = 0.f;
#pragma unroll
        for (int ww = 0; ww < 8; ww++) s += sm->part[2 * ww + rr][0][c];
        sm->X[rr][c] = s;                              // X region now Ssum
    }
    __syncthreads();
    mbar_wait(mB, 0);                                  // w2[1,0] (3rd use)
    {   float4 a0 = {}, a1 = {};
#pragma unroll
        for (int kk = 0; kk < 8; kk++) {
            int k = w * 8 + kk;
            float4 wv = WB4[k * 32 + lane];
            a0 = f4fma(sm->X[0][k], wv, a0);
            a1 = f4fma(sm->X[1][k], wv, a1);
        }
        ((float4*)sm->part[w][0])[lane] = a0;
        ((float4*)sm->part[w][1])[lane] = a1;
    }
    __syncthreads();
    {   // epilogue (all threads run syncs; stores guarded)
        int rre = (tid >> 7) & 1, c = tid & 127;
        bool act = tid < 256;
        int lst = 2 * i + rre, row = row0 + lst;
        float a2 = 0.f;
#pragma unroll
        for (int ww = 0; ww < 16; ww++) a2 += sm->part[ww][rre][c];
        float sf = (float)sm->selfS[lst];
        float res = g_u[row * DD + c] + sf * g_d[row * DD + c]
                  + a2 + (float)sm->cnts[lst] * b2[2 * DD + c];
#pragma unroll
        for (int rr2 = 0; rr2 < 2; rr2++) {
            if (sm->selfS[2 * i + rr2]) {              // block-uniform, rare
                int rowx = row0 + 2 * i + rr2;
                if (tid < 128) {
                    sm->D[0][tid] = fmaxf(g_UD[0][rowx * DD + tid]
                                         + g_UD[1][rowx * DD + tid]
                                         + b1[2 * DD + tid], 0.f);
                    sm->D[1][tid] = fmaxf(g_UD[2][rowx * DD + tid]
                                         + g_UD[3][rowx * DD + tid]
                                         + b1[3 * DD + tid], 0.f);
                }
                __syncthreads();
                float d0 = 0.f, d1 = 0.f;
#pragma unroll 4
                for (int k = 0; k < DD; k++) {
                    d0 = fmaf(sm->D[0][k], w2[2 * 16384 + k * DD + c], d0);
                    d1 = fmaf(sm->D[1][k], w2[3 * 16384 + k * DD + c], d1);
                }
                if (act && rre == rr2)
                    res += (d1 + b2[3 * DD + c]) - (d0 + b2[2 * DD + c]);
                __syncthreads();
            }
        }
        if (act) out[row * DD + c] = res;
    }
    // restore adjacency for the next graph replay (i==0 blocks cover all rows)
    __syncthreads();
    if (i == 0 && tid < 32) g_adj[row0 * 8 + tid] = 0u;
}

extern "C" void kernel_launch(void* const* d_in, const int* in_sizes, int n_in,
                              void* d_out, int out_size) {
    const float* x  = (const float*)d_in[0];
    const float* w1 = (const float*)d_in[1];
    const float* b1 = (const float*)d_in[2];
    const float* w2 = (const float*)d_in[3];
    const float* b2 = (const float*)d_in[4];
    const int*   ei = (const int*)d_in[5];   // dtype sniffed on device
    int E = in_sizes[5] / 2;
    float* out = (float*)d_out;

    static bool attrSet = false;
    if (!attrSet) {
        cudaFuncSetAttribute(k_fused, cudaFuncAttributeMaxDynamicSharedMemorySize,
                             (int)sizeof(DynSmem));
        attrSet = true;
    }
    k_fused<<<NB, NT, sizeof(DynSmem)>>>(ei, E, x, w1, b1, w2, b2, out);
}

// round 13
// speedup vs baseline: 1.1651x; 1.1651x over previous
#include <cuda_runtime.h>

// IDGNN restructured (math validated R2-R11, rel_err ~2e-7):
//   p_i = MLP_{0,i}(x);  u = x + A*p0;  d = p1 - p0
//   Un_i = u*W1e[1,i]; Dt_i = d*W1e[1,i]   (W1e[k] = w1[k]+w1[k+128])
//   S_t = sum_{n in N(t)} relu(Un0[n] + Dt0[t] + b1[1,0])
//   out[t] = u_t + self_t*d_t + S_t*w2[1,0] + deg_t*b2[1,0]  (+ rare self fix)
// R13 = R12 + alignment fix: ALL shared arrays accessed via float4 casts are
// explicitly __align__(16) (R12's k_out had Sp at smem offset 2056 -> trap).

#define NN 256
#define DD 128

// ---- device scratch (zero-init at load; g_adj restored by k_self) ----
__device__ unsigned g_adj[NN * 8];
__device__ __align__(16) float g_W1e[4 * DD * DD];
__device__ __align__(16) float g_p0[NN * DD];
__device__ __align__(16) float g_p1[NN * DD];
__device__ __align__(16) float g_u [NN * DD];
__device__ __align__(16) float g_d [NN * DD];
__device__ __align__(16) float g_UD[4][NN * DD];   // 0:Un0 1:Dt0 2:Un1 3:Dt1

__device__ __forceinline__ float4 f4add(float4 a, float4 b) {
    return make_float4(a.x + b.x, a.y + b.y, a.z + b.z, a.w + b.w);
}
__device__ __forceinline__ float4 f4fma(float s, float4 w, float4 a) {
    return make_float4(fmaf(s, w.x, a.x), fmaf(s, w.y, a.y),
                       fmaf(s, w.z, a.z), fmaf(s, w.w, a.w));
}
__device__ __forceinline__ float4 f4relu(float4 a) {
    return make_float4(fmaxf(a.x, 0.f), fmaxf(a.y, 0.f),
                       fmaxf(a.z, 0.f), fmaxf(a.w, 0.f));
}

// Expand g_adj[row] bitmask into nbr[] (full warp). Returns count.
__device__ __forceinline__ int build_list(int row, int* nbr) {
    int lane = threadIdx.x & 31;
    unsigned word = (lane < 8) ? g_adj[row * 8 + lane] : 0u;
    int pc = __popc(word);
    int inc = pc;
#pragma unroll
    for (int off = 1; off < 8; off <<= 1) {
        int v = __shfl_up_sync(0xffffffffu, inc, off);
        if (lane >= off) inc += v;
    }
    int base = inc - pc;
    if (lane < 8) {
        unsigned bits = word; int o = base;
        while (bits) { int b = __ffs(bits) - 1; bits &= bits - 1; nbr[o++] = lane * 32 + b; }
    }
    return __shfl_sync(0xffffffffu, inc, 7);
}

// ---------------------------------------------------------------------------
// K0: blocks [0,16): edge scatter. blocks [16,144): W1e = w1[:128]+w1[128:].
// ---------------------------------------------------------------------------
__global__ void __launch_bounds__(128)
k_build(const int* __restrict__ ei32, int E, const float4* __restrict__ w14) {
    int tid = threadIdx.x;
    if (blockIdx.x < 16) {
        // dtype sniff: int64 node ids (<256, nonneg) => odd int32 words zero
        int probe = (2 * tid + 1 < 2 * E) ? ei32[2 * tid + 1] : 0;
        int is64 = __syncthreads_and(probe == 0);
        for (int e = blockIdx.x * 128 + tid; e < E; e += 16 * 128) {
            int a, b;
            if (is64) { a = ei32[2 * e]; b = ei32[2 * (E + e)]; }
            else      { a = ei32[e];     b = ei32[E + e]; }
            a &= 255; b &= 255;
            atomicOr(&g_adj[a * 8 + (b >> 5)], 1u << (b & 31));
            atomicOr(&g_adj[b * 8 + (a >> 5)], 1u << (a & 31));
        }
        return;
    }
    int j  = (blockIdx.x - 16) * 128 + tid;   // float4 index in [0,16384)
    int li = j >> 12, rem = j & 4095;
    float4 a = w14[li * 8192 + rem];
    float4 b = w14[li * 8192 + rem + 4096];
    ((float4*)g_W1e)[j] = f4add(a, b);
}

// ---------------------------------------------------------------------------
// K1: p_i = (relu(x*W1e[0,i]+b1[0,i]))*w2[0,i]+b2[0,i].
// grid=(64,2) block=128. 4 rows/block, split-K float4.
// ---------------------------------------------------------------------------
__global__ void __launch_bounds__(128, 1)
k_p(const float4* __restrict__ x4, const float* __restrict__ b1,
    const float4* __restrict__ w24, const float* __restrict__ b2) {
    int i = blockIdx.y, row0 = blockIdx.x * 4;
    int tid = threadIdx.x, lane = tid & 31, w = tid >> 5;
    __shared__ __align__(16) float S[4][DD];
    __shared__ __align__(16) float red[4][4][DD];

    ((float4*)S[w])[lane] = x4[(row0 + w) * 32 + lane];
    __syncthreads();

    const float4* W = (const float4*)g_W1e + i * 4096;   // W1e[0,i]
    float4 acc[4] = {};
#pragma unroll
    for (int kk = 0; kk < 32; kk++) {
        int k = w * 32 + kk;
        float4 wv = W[k * 32 + lane];
#pragma unroll
        for (int r = 0; r < 4; r++) acc[r] = f4fma(S[r][k], wv, acc[r]);
    }
#pragma unroll
    for (int r = 0; r < 4; r++) ((float4*)red[w][r])[lane] = acc[r];
    __syncthreads();

    {
        float b1v = b1[i * DD + tid];
        float h[4];
#pragma unroll
        for (int r = 0; r < 4; r++)
            h[r] = red[0][r][tid] + red[1][r][tid] + red[2][r][tid] + red[3][r][tid] + b1v;
        __syncthreads();
#pragma unroll
        for (int r = 0; r < 4; r++) S[r][tid] = fmaxf(h[r], 0.f);
    }
    __syncthreads();

    const float4* W2 = w24 + i * 4096;                    // w2[0,i]
    float4 a2[4] = {};
#pragma unroll
    for (int kk = 0; kk < 32; kk++) {
        int k = w * 32 + kk;
        float4 wv = W2[k * 32 + lane];
#pragma unroll
        for (int r = 0; r < 4; r++) a2[r] = f4fma(S[r][k], wv, a2[r]);
    }
#pragma unroll
    for (int r = 0; r < 4; r++) ((float4*)red[w][r])[lane] = a2[r];
    __syncthreads();

    float b2v = b2[i * DD + tid];
    float* dst = i ? g_p1 : g_p0;
#pragma unroll
    for (int r = 0; r < 4; r++)
        dst[(row0 + r) * DD + tid] =
            red[0][r][tid] + red[1][r][tid] + red[2][r][tid] + red[3][r][tid] + b2v;
}

// ---------------------------------------------------------------------------
// K2: u = x + gather(p0), d = p1-p0; Un_i = u*W1e[1,i], Dt_i = d*W1e[1,i].
// grid=(64,2) block=128. 4 rows/block; warp-per-row float4 gather.
// ---------------------------------------------------------------------------
__global__ void __launch_bounds__(128, 1)
k_ud(const float4* __restrict__ x4) {
    int i = blockIdx.y, row0 = blockIdx.x * 4;
    int tid = threadIdx.x, lane = tid & 31, w = tid >> 5;
    __shared__ __align__(16) float U[4][DD];
    __shared__ __align__(16) float D[4][DD];
    __shared__ __align__(16) float red[4][8][DD];
    __shared__ int nbr[4][NN];

    int row = row0 + w;
    int cn = build_list(row, nbr[w]);

    const float4* p04 = (const float4*)g_p0;
    float4 a0 = x4[row * 32 + lane];
    float4 a1 = {}, a2 = {}, a3 = {};
    int j = 0;
    for (; j + 4 <= cn; j += 4) {
        a0 = f4add(a0, p04[nbr[w][j]     * 32 + lane]);
        a1 = f4add(a1, p04[nbr[w][j + 1] * 32 + lane]);
        a2 = f4add(a2, p04[nbr[w][j + 2] * 32 + lane]);
        a3 = f4add(a3, p04[nbr[w][j + 3] * 32 + lane]);
    }
    for (; j < cn; j++) a0 = f4add(a0, p04[nbr[w][j] * 32 + lane]);
    float4 u = f4add(f4add(a0, a1), f4add(a2, a3));
    ((float4*)U[w])[lane] = u;

    float4 p1v = ((const float4*)g_p1)[row * 32 + lane];
    float4 p0v = p04[row * 32 + lane];
    float4 dv = make_float4(p1v.x - p0v.x, p1v.y - p0v.y, p1v.z - p0v.z, p1v.w - p0v.w);
    ((float4*)D[w])[lane] = dv;
    if (i == 0) {
        ((float4*)g_u)[row * 32 + lane] = u;
        ((float4*)g_d)[row * 32 + lane] = dv;
    }
    __syncthreads();

    const float4* W = (const float4*)g_W1e + (2 + i) * 4096;   // W1e[1,i]
    float4 aU[4] = {}, aD[4] = {};
#pragma unroll
    for (int kk = 0; kk < 32; kk++) {
        int k = w * 32 + kk;
        float4 wv = W[k * 32 + lane];
#pragma unroll
        for (int r = 0; r < 4; r++) {
            aU[r] = f4fma(U[r][k], wv, aU[r]);
            aD[r] = f4fma(D[r][k], wv, aD[r]);
        }
    }
#pragma unroll
    for (int r = 0; r < 4; r++) {
        ((float4*)red[w][r])[lane]     = aU[r];
        ((float4*)red[w][4 + r])[lane] = aD[r];
    }
    __syncthreads();

#pragma unroll
    for (int v = 0; v < 8; v++) {
        float s = red[0][v][tid] + red[1][v][tid] + red[2][v][tid] + red[3][v][tid];
        int r = v & 3, isD = v >> 2;
        g_UD[2 * i + isD][(row0 + r) * DD + tid] = s;
    }
}

// ---------------------------------------------------------------------------
// K3: S_t relu-gather + final matvec + base output. 128 blocks x 2 rows.
// Pure float4; NO scalar loops, NO conditional syncs. Self fix is in k_self.
// ---------------------------------------------------------------------------
__global__ void __launch_bounds__(128, 1)
k_out(const float* __restrict__ b1, const float4* __restrict__ w24,
      const float* __restrict__ b2, float* __restrict__ out) {
    int t0 = blockIdx.x * 2;
    int tid = threadIdx.x, lane = tid & 31, w = tid >> 5;
    __shared__ __align__(16) float Sp[2][2][DD];     // [half][r][c]
    __shared__ __align__(16) float red[2][2][DD];    // [q][r][c]
    __shared__ int nbr[2][NN];
    __shared__ int cnts[2];

    if (w < 2) {
        int cn = build_list(t0 + w, nbr[w]);
        if (lane == 0) cnts[w] = cn;
    }
    __syncthreads();
    {   // relu-gather: warp (r = w&1, half = w>>1) splits list mod 2
        int r = w & 1, half = w >> 1;
        int row = t0 + r;
        const float4* UD0 = (const float4*)g_UD[0];
        float4 pre = f4add(((const float4*)g_UD[1])[row * 32 + lane],
                           ((const float4*)(b1 + 2 * DD))[lane]);
        int cn = cnts[r];
        float4 s0 = {}, s1 = {};
        int j = half;
        for (; j + 2 < cn; j += 4) {
            s0 = f4add(s0, f4relu(f4add(UD0[nbr[r][j]     * 32 + lane], pre)));
            s1 = f4add(s1, f4relu(f4add(UD0[nbr[r][j + 2] * 32 + lane], pre)));
        }
        if (j < cn) s0 = f4add(s0, f4relu(f4add(UD0[nbr[r][j] * 32 + lane], pre)));
        ((float4*)Sp[half][r])[lane] = f4add(s0, s1);
    }
    __syncthreads();
    {   // final matvec vs w2[1,0]: warp (r = w&1, q = w>>1), K split in halves
        int r = w & 1, q = w >> 1;
        float4 acc = {};
#pragma unroll
        for (int kk = 0; kk < 64; kk++) {
            int k = q * 64 + kk;
            float4 wv = w24[8192 + k * 32 + lane];
            acc = f4fma(Sp[0][r][k] + Sp[1][r][k], wv, acc);
        }
        ((float4*)red[q][r])[lane] = acc;
    }
    __syncthreads();
    {   // epilogue: thread c, both rows
        int c = tid;
        float b20 = b2[2 * DD + c];
#pragma unroll
        for (int r = 0; r < 2; r++) {
            int row = t0 + r;
            unsigned diag = g_adj[row * 8 + (row >> 5)];
            float sf = (float)((diag >> (row & 31)) & 1);
            float res = g_u[row * DD + c] + sf * g_d[row * DD + c]
                      + red[0][r][c] + red[1][r][c] + (float)cnts[r] * b20;
            out[row * DD + c] = res;
        }
    }
}

// ---------------------------------------------------------------------------
// K4: self-loop correction (rare, ~8/256 rows) + g_adj restore. 64 blocks.
//   out[t] += (relu(Un1+Dt1+b1[1,1]).w2[1,1]+b2[1,1])
//           - (relu(Un0+Dt0+b1[1,0]).w2[1,0]+b2[1,0])   for rows with A[t,t]=1
// ---------------------------------------------------------------------------
__global__ void __launch_bounds__(128, 1)
k_self(const float* __restrict__ b1, const float4* __restrict__ w24,
       const float* __restrict__ b2, float* __restrict__ out) {
    int t0 = blockIdx.x * 4;
    int tid = threadIdx.x, lane = tid & 31, w = tid >> 5;
    __shared__ __align__(16) float H0[DD];
    __shared__ __align__(16) float H1[DD];
    __shared__ __align__(16) float red[4][2][DD];
    __shared__ unsigned flagsS;

    if (tid == 0) {
        unsigned f = 0;
#pragma unroll
        for (int r = 0; r < 4; r++) {
            int row = t0 + r;
            f |= ((g_adj[row * 8 + (row >> 5)] >> (row & 31)) & 1u) << r;
        }
        flagsS = f;
    }
    __syncthreads();
    unsigned flags = flagsS;

#pragma unroll
    for (int r = 0; r < 4; r++) {
        if ((flags >> r) & 1u) {           // block-uniform
            int row = t0 + r;
            H0[tid] = fmaxf(g_UD[0][row * DD + tid] + g_UD[1][row * DD + tid]
                            + b1[2 * DD + tid], 0.f);
            H1[tid] = fmaxf(g_UD[2][row * DD + tid] + g_UD[3][row * DD + tid]
                            + b1[3 * DD + tid], 0.f);
            __syncthreads();
            float4 a0 = {}, a1 = {};
#pragma unroll
            for (int kk = 0; kk < 32; kk++) {
                int k = w * 32 + kk;
                a0 = f4fma(H0[k], w24[8192  + k * 32 + lane], a0);  // w2[1,0]
                a1 = f4fma(H1[k], w24[12288 + k * 32 + lane], a1);  // w2[1,1]
            }
            ((float4*)red[w][0])[lane] = a0;
            ((float4*)red[w][1])[lane] = a1;
            __syncthreads();
            {
                int c = tid;
                float d0 = red[0][0][c] + red[1][0][c] + red[2][0][c] + red[3][0][c];
                float d1 = red[0][1][c] + red[1][1][c] + red[2][1][c] + red[3][1][c];
                out[row * DD + c] += (d1 + b2[3 * DD + c]) - (d0 + b2[2 * DD + c]);
            }
            __syncthreads();
        }
    }
    // restore adjacency rows t0..t0+3 for the next graph replay
    if (tid < 32) g_adj[t0 * 8 + tid] = 0u;
}

extern "C" void kernel_launch(void* const* d_in, const int* in_sizes, int n_in,
                              void* d_out, int out_size) {
    const float* x  = (const float*)d_in[0];
    const float* w1 = (const float*)d_in[1];
    const float* b1 = (const float*)d_in[2];
    const float* w2 = (const float*)d_in[3];
    const float* b2 = (const float*)d_in[4];
    const int*   ei = (const int*)d_in[5];   // dtype sniffed on device
    int E = in_sizes[5] / 2;
    float* out = (float*)d_out;

    k_build<<<144, 128>>>(ei, E, (const float4*)w1);
    k_p    <<<dim3(64, 2), 128>>>((const float4*)x, b1, (const float4*)w2, b2);
    k_ud   <<<dim3(64, 2), 128>>>((const float4*)x);
    k_out  <<<128, 128>>>(b1, (const float4*)w2, b2, out);
    k_self <<<64, 128>>>(b1, (const float4*)w2, b2, out);
}

// round 14
// speedup vs baseline: 1.4654x; 1.2578x over previous
#include <cuda_runtime.h>

// IDGNN restructured (math validated R2-R13, rel_err ~2e-7):
//   p_i = MLP_{0,i}(x);  u = x + A*p0;  d = p1 - p0
//   Un_i = u*W1e[1,i]; Dt_i = d*W1e[1,i]   (W1e[k] = w1[k]+w1[k+128], inline fold)
//   S_t = sum_{n in N(t)} relu(Un0[n] + Dt0[t] + b1[1,0])
//   out[t] = u_t + self_t*d_t + S_t*w2[1,0] + deg_t*b2[1,0]
//            + self_t*( corr1_t - corr0_t ),  corr_i = relu(Un_i+Dt_i+b1[1,i]).w2[1,i]+b2[1,i]
// R14: 5 kernels -> 3. Fold inline (k_build gone, scatter rides in k_p grid);
// self-correction computed unconditionally in k_ud into g_corr[i] (disjoint
// slots, no atomics); k_out = 256 blocks x 1 row, applies sf*(corr1-corr0),
// restores g_adj. All float4-cast smem arrays explicitly __align__(16).

#define NN 256
#define DD 128

// ---- device scratch (zero-init at load; g_adj restored by k_out) ----
__device__ unsigned g_adj[NN * 8];
__device__ __align__(16) float g_p0[NN * DD];
__device__ __align__(16) float g_p1[NN * DD];
__device__ __align__(16) float g_u [NN * DD];
__device__ __align__(16) float g_d [NN * DD];
__device__ __align__(16) float g_UD[4][NN * DD];   // 0:Un0 1:Dt0 2:Un1 3:Dt1
__device__ __align__(16) float g_corr[2][NN * DD]; // d_i + b2[1,i] per row

__device__ __forceinline__ float4 f4add(float4 a, float4 b) {
    return make_float4(a.x + b.x, a.y + b.y, a.z + b.z, a.w + b.w);
}
__device__ __forceinline__ float4 f4fma(float s, float4 w, float4 a) {
    return make_float4(fmaf(s, w.x, a.x), fmaf(s, w.y, a.y),
                       fmaf(s, w.z, a.z), fmaf(s, w.w, a.w));
}
__device__ __forceinline__ float4 f4relu(float4 a) {
    return make_float4(fmaxf(a.x, 0.f), fmaxf(a.y, 0.f),
                       fmaxf(a.z, 0.f), fmaxf(a.w, 0.f));
}

// Expand g_adj[row] bitmask into nbr[] (full warp). Returns count.
__device__ __forceinline__ int build_list(int row, int* nbr) {
    int lane = threadIdx.x & 31;
    unsigned word = (lane < 8) ? g_adj[row * 8 + lane] : 0u;
    int pc = __popc(word);
    int inc = pc;
#pragma unroll
    for (int off = 1; off < 8; off <<= 1) {
        int v = __shfl_up_sync(0xffffffffu, inc, off);
        if (lane >= off) inc += v;
    }
    int base = inc - pc;
    if (lane < 8) {
        unsigned bits = word; int o = base;
        while (bits) { int b = __ffs(bits) - 1; bits &= bits - 1; nbr[o++] = lane * 32 + b; }
    }
    return __shfl_sync(0xffffffffu, inc, 7);
}

// ---------------------------------------------------------------------------
// K1: blocks [0,128): p_i = (relu(x*W1e[0,i]+b1[0,i]))*w2[0,i]+b2[0,i]
//     (inline fold, 4 rows/block, split-K float4).
//     blocks [128,144): edge scatter into g_adj (consumed first by k_ud).
// ---------------------------------------------------------------------------
__global__ void __launch_bounds__(128, 1)
k_p(const int* __restrict__ ei32, int E,
    const float4* __restrict__ x4, const float4* __restrict__ w14,
    const float* __restrict__ b1, const float4* __restrict__ w24,
    const float* __restrict__ b2) {
    int tid = threadIdx.x, lane = tid & 31, w = tid >> 5;
    if (blockIdx.x >= 128) {                  // edge scatter
        // dtype sniff: int64 node ids (<256, nonneg) => odd int32 words zero
        int probe = (2 * tid + 1 < 2 * E) ? ei32[2 * tid + 1] : 0;
        int is64 = __syncthreads_and(probe == 0);
        for (int e = (blockIdx.x - 128) * 128 + tid; e < E; e += 16 * 128) {
            int a, b;
            if (is64) { a = ei32[2 * e]; b = ei32[2 * (E + e)]; }
            else      { a = ei32[e];     b = ei32[E + e]; }
            a &= 255; b &= 255;
            atomicOr(&g_adj[a * 8 + (b >> 5)], 1u << (b & 31));
            atomicOr(&g_adj[b * 8 + (a >> 5)], 1u << (a & 31));
        }
        return;
    }
    int i = blockIdx.x >> 6, row0 = (blockIdx.x & 63) * 4;
    __shared__ __align__(16) float S[4][DD];
    __shared__ __align__(16) float red[4][4][DD];

    ((float4*)S[w])[lane] = x4[(row0 + w) * 32 + lane];
    __syncthreads();

    const float4* W = w14 + i * 8192;         // w1[0,i] : [256,128]
    float4 acc[4] = {};
#pragma unroll
    for (int kk = 0; kk < 32; kk++) {
        int k = w * 32 + kk;
        float4 we = f4add(W[k * 32 + lane], W[(k + 128) * 32 + lane]);
#pragma unroll
        for (int r = 0; r < 4; r++) acc[r] = f4fma(S[r][k], we, acc[r]);
    }
#pragma unroll
    for (int r = 0; r < 4; r++) ((float4*)red[w][r])[lane] = acc[r];
    __syncthreads();

    {
        float b1v = b1[i * DD + tid];
        float h[4];
#pragma unroll
        for (int r = 0; r < 4; r++)
            h[r] = red[0][r][tid] + red[1][r][tid] + red[2][r][tid] + red[3][r][tid] + b1v;
        __syncthreads();
#pragma unroll
        for (int r = 0; r < 4; r++) S[r][tid] = fmaxf(h[r], 0.f);
    }
    __syncthreads();

    const float4* W2 = w24 + i * 4096;        // w2[0,i]
    float4 a2[4] = {};
#pragma unroll
    for (int kk = 0; kk < 32; kk++) {
        int k = w * 32 + kk;
        float4 wv = W2[k * 32 + lane];
#pragma unroll
        for (int r = 0; r < 4; r++) a2[r] = f4fma(S[r][k], wv, a2[r]);
    }
#pragma unroll
    for (int r = 0; r < 4; r++) ((float4*)red[w][r])[lane] = a2[r];
    __syncthreads();

    float b2v = b2[i * DD + tid];
    float* dst = i ? g_p1 : g_p0;
#pragma unroll
    for (int r = 0; r < 4; r++)
        dst[(row0 + r) * DD + tid] =
            red[0][r][tid] + red[1][r][tid] + red[2][r][tid] + red[3][r][tid] + b2v;
}

// ---------------------------------------------------------------------------
// K2: u = x + gather(p0), d = p1-p0; Un_i/Dt_i = {u,d}*W1e[1,i] (inline fold);
// PLUS self-correction dot: g_corr[i][row] = relu(Un_i+Dt_i+b1[1,i]).w2[1,i]+b2[1,i]
// grid=(64,2) block=128. 4 rows/block; warp-per-row float4 gather.
// ---------------------------------------------------------------------------
__global__ void __launch_bounds__(128, 1)
k_ud(const float4* __restrict__ x4, const float4* __restrict__ w14,
     const float* __restrict__ b1, const float4* __restrict__ w24,
     const float* __restrict__ b2) {
    int i = blockIdx.y, row0 = blockIdx.x * 4;
    int tid = threadIdx.x, lane = tid & 31, w = tid >> 5;
    __shared__ __align__(16) float U[4][DD];
    __shared__ __align__(16) float D[4][DD];
    __shared__ __align__(16) float red[4][8][DD];
    __shared__ int nbr[4][NN];

    int row = row0 + w;
    int cn = build_list(row, nbr[w]);

    const float4* p04 = (const float4*)g_p0;
    float4 a0 = x4[row * 32 + lane];
    float4 a1 = {}, a2 = {}, a3 = {};
    int j = 0;
    for (; j + 4 <= cn; j += 4) {
        a0 = f4add(a0, p04[nbr[w][j]     * 32 + lane]);
        a1 = f4add(a1, p04[nbr[w][j + 1] * 32 + lane]);
        a2 = f4add(a2, p04[nbr[w][j + 2] * 32 + lane]);
        a3 = f4add(a3, p04[nbr[w][j + 3] * 32 + lane]);
    }
    for (; j < cn; j++) a0 = f4add(a0, p04[nbr[w][j] * 32 + lane]);
    float4 u = f4add(f4add(a0, a1), f4add(a2, a3));
    ((float4*)U[w])[lane] = u;

    float4 p1v = ((const float4*)g_p1)[row * 32 + lane];
    float4 p0v = p04[row * 32 + lane];
    float4 dv = make_float4(p1v.x - p0v.x, p1v.y - p0v.y, p1v.z - p0v.z, p1v.w - p0v.w);
    ((float4*)D[w])[lane] = dv;
    if (i == 0) {
        ((float4*)g_u)[row * 32 + lane] = u;
        ((float4*)g_d)[row * 32 + lane] = dv;
    }
    __syncthreads();

    const float4* W = w14 + (2 + i) * 8192;   // w1[1,i], inline fold
    float4 aU[4] = {}, aD[4] = {};
#pragma unroll
    for (int kk = 0; kk < 32; kk++) {
        int k = w * 32 + kk;
        float4 we = f4add(W[k * 32 + lane], W[(k + 128) * 32 + lane]);
#pragma unroll
        for (int r = 0; r < 4; r++) {
            aU[r] = f4fma(U[r][k], we, aU[r]);
            aD[r] = f4fma(D[r][k], we, aD[r]);
        }
    }
#pragma unroll
    for (int r = 0; r < 4; r++) {
        ((float4*)red[w][r])[lane]     = aU[r];
        ((float4*)red[w][4 + r])[lane] = aD[r];
    }
    __syncthreads();

    float unv[4], dtv[4];
#pragma unroll
    for (int v = 0; v < 8; v++) {
        float s = red[0][v][tid] + red[1][v][tid] + red[2][v][tid] + red[3][v][tid];
        int r = v & 3, isD = v >> 2;
        g_UD[2 * i + isD][(row0 + r) * DD + tid] = s;
        if (isD) dtv[r] = s; else unv[r] = s;
    }
    // ---- self-correction dot for these 4 rows (unconditional; masked later)
    {
        float b1v = b1[(2 + i) * DD + tid];
#pragma unroll
        for (int r = 0; r < 4; r++)
            U[r][tid] = fmaxf(unv[r] + dtv[r] + b1v, 0.f);   // H_i (U reused)
    }
    __syncthreads();
    const float4* W2 = w24 + (2 + i) * 4096;  // w2[1,i]
    float4 ac[4] = {};
#pragma unroll
    for (int kk = 0; kk < 32; kk++) {
        int k = w * 32 + kk;
        float4 wv = W2[k * 32 + lane];
#pragma unroll
        for (int r = 0; r < 4; r++) ac[r] = f4fma(U[r][k], wv, ac[r]);
    }
#pragma unroll
    for (int r = 0; r < 4; r++) ((float4*)red[w][r])[lane] = ac[r];
    __syncthreads();
    {
        float b2v = b2[(2 + i) * DD + tid];
#pragma unroll
        for (int r = 0; r < 4; r++)
            g_corr[i][(row0 + r) * DD + tid] =
                red[0][r][tid] + red[1][r][tid] + red[2][r][tid] + red[3][r][tid] + b2v;
    }
}

// ---------------------------------------------------------------------------
// K3: S_t relu-gather + final matvec + epilogue (incl. corr) + g_adj restore.
// 256 blocks x 1 row. Pure float4, no conditional syncs.
// ---------------------------------------------------------------------------
__global__ void __launch_bounds__(128, 1)
k_out(const float* __restrict__ b1, const float4* __restrict__ w24,
      const float* __restrict__ b2, float* __restrict__ out) {
    int t = blockIdx.x;
    int tid = threadIdx.x, lane = tid & 31, w = tid >> 5;
    __shared__ __align__(16) float Sp[4][DD];    // gather partials per warp
    __shared__ __align__(16) float Ssum[DD];
    __shared__ __align__(16) float red[4][DD];
    __shared__ int nbr[NN];
    __shared__ int cntS;

    if (w == 0) {
        int cn = build_list(t, nbr);
        if (lane == 0) cntS = cn;
    }
    __syncthreads();
    int cn = cntS;
    {   // relu-gather: warp w takes list positions w, w+4, w+8, ...
        const float4* UD0 = (const float4*)g_UD[0];
        float4 pre = f4add(((const float4*)g_UD[1])[t * 32 + lane],
                           ((const float4*)(b1 + 2 * DD))[lane]);
        float4 s0 = {}, s1 = {};
        int j = w;
        for (; j + 4 < cn; j += 8) {
            s0 = f4add(s0, f4relu(f4add(UD0[nbr[j]     * 32 + lane], pre)));
            s1 = f4add(s1, f4relu(f4add(UD0[nbr[j + 4] * 32 + lane], pre)));
        }
        if (j < cn) s0 = f4add(s0, f4relu(f4add(UD0[nbr[j] * 32 + lane], pre)));
        ((float4*)Sp[w])[lane] = f4add(s0, s1);
    }
    __syncthreads();
    if (tid < DD)
        Ssum[tid] = Sp[0][tid] + Sp[1][tid] + Sp[2][tid] + Sp[3][tid];
    __syncthreads();
    {   // final matvec vs w2[1,0]: warp w covers k in [w*32, w*32+32)
        float4 acc = {};
#pragma unroll
        for (int kk = 0; kk < 32; kk++) {
            int k = w * 32 + kk;
            float4 wv = w24[8192 + k * 32 + lane];
            acc = f4fma(Ssum[k], wv, acc);
        }
        ((float4*)red[w])[lane] = acc;
    }
    __syncthreads();
    {   // epilogue
        int c = tid;
        unsigned diag = g_adj[t * 8 + (t >> 5)];
        float sf = (float)((diag >> (t & 31)) & 1);
        float a2 = red[0][c] + red[1][c] + red[2][c] + red[3][c];
        float res = g_u[t * DD + c] + sf * g_d[t * DD + c]
                  + a2 + (float)cn * b2[2 * DD + c]
                  + sf * (g_corr[1][t * DD + c] - g_corr[0][t * DD + c]);
        out[t * DD + c] = res;
    }
    // restore adjacency row t for the next graph replay
    __syncthreads();
    if (tid < 8) g_adj[t * 8 + tid] = 0u;
}

extern "C" void kernel_launch(void* const* d_in, const int* in_sizes, int n_in,
                              void* d_out, int out_size) {
    const float* x  = (const float*)d_in[0];
    const float* w1 = (const float*)d_in[1];
    const float* b1 = (const float*)d_in[2];
    const float* w2 = (const float*)d_in[3];
    const float* b2 = (const float*)d_in[4];
    const int*   ei = (const int*)d_in[5];   // dtype sniffed on device
    int E = in_sizes[5] / 2;
    float* out = (float*)d_out;

    k_p  <<<144, 128>>>(ei, E, (const float4*)x, (const float4*)w1,
                        b1, (const float4*)w2, b2);
    k_ud <<<dim3(64, 2), 128>>>((const float4*)x, (const float4*)w1,
                                b1, (const float4*)w2, b2);
    k_out<<<256, 128>>>(b1, (const float4*)w2, b2, out);
}